// round 3
// baseline (speedup 1.0000x reference)
#include <cuda_runtime.h>
#include <cuda_fp16.h>
#include <cstdint>

#define NMAX 50000
#define EMAX 800000
#define H 64

// Scratch (static device arrays; no dynamic allocation allowed)
__device__ __half g_h[NMAX * H];      // fp16 messages g = (X@W)*dinv_src
__device__ float  g_acc[NMAX * H];    // fp32 aggregated output per layer
__device__ int    g_cnt[NMAX];        // incoming-edge count (excl self loop)
__device__ float  g_dinv[NMAX];
__device__ int    g_off[NMAX];        // CSR offsets (exclusive prefix of cnt)
__device__ int    g_cur[NMAX];        // fill cursors
__device__ int    g_csr[EMAX];        // CSR-sorted source ids per dst
__device__ float  g_colsum[H];
__device__ int    g_is64;

// decoupled-lookback scan state
__device__ int          g_ticket;
__device__ volatile int g_state[64];   // 0=invalid 1=aggregate 2=prefix
__device__ volatile int g_aggval[64];
__device__ volatile int g_prefval[64];

// ---------------------------------------------------------------------------
// Zero counters/scan-state + detect int64 vs int32 edge_index.
// int64 values < 50000 => all odd 32-bit words zero.
// ---------------------------------------------------------------------------
__global__ void zero_kernel(const unsigned int* __restrict__ w, int N) {
    int i = blockIdx.x * blockDim.x + threadIdx.x;
    if (i < N) g_cnt[i] = 0;
    if (i < H) g_colsum[i] = 0.f;
    if (i < 64) { ((int*)g_state)[i] = 0; }
    if (i == 0) g_ticket = 0;
    if (blockIdx.x == 0 && threadIdx.x < 32) {
        unsigned int v = w[2 * threadIdx.x + 1] | w[2 * (threadIdx.x + 32) + 1];
        int all0 = __all_sync(0xffffffffu, v == 0u);
        if (threadIdx.x == 0) g_is64 = all0;
    }
}

// Histogram destinations only (src decoded later in fill).
__global__ void hist_kernel(const int* __restrict__ ei, int E) {
    int e = blockIdx.x * blockDim.x + threadIdx.x;
    if (e >= E) return;
    int d = g_is64 ? ei[2 * E + 2 * e] : ei[E + e];
    atomicAdd(&g_cnt[d], 1);
}

// ---------------------------------------------------------------------------
// Single-kernel exclusive scan (decoupled lookback, ticket-ordered).
// 1024 items per block. Also derives g_cur and g_dinv in the writeback.
// ---------------------------------------------------------------------------
__global__ void scan_kernel(int N) {
    __shared__ int s_bid;
    __shared__ int s_warp[8];
    __shared__ int s_exc;
    int t = threadIdx.x;
    if (t == 0) s_bid = atomicAdd(&g_ticket, 1);
    __syncthreads();
    int bid = s_bid;

    int base = bid * 1024 + t * 4;
    int v[4], tsum = 0;
#pragma unroll
    for (int j = 0; j < 4; j++) {
        int idx = base + j;
        v[j] = (idx < N) ? g_cnt[idx] : 0;
        tsum += v[j];
    }
    int lane = t & 31, w = t >> 5;
    int x = tsum;
#pragma unroll
    for (int o = 1; o < 32; o <<= 1) {
        int y = __shfl_up_sync(0xffffffffu, x, o);
        if (lane >= o) x += y;
    }
    if (lane == 31) s_warp[w] = x;
    __syncthreads();

    if (t == 0) {
        int total = 0;
#pragma unroll
        for (int i = 0; i < 8; i++) { int tmp = s_warp[i]; s_warp[i] = total; total += tmp; }
        int exc = 0;
        if (bid == 0) {
            g_prefval[0] = total;
            __threadfence();
            g_state[0] = 2;
        } else {
            g_aggval[bid] = total;
            __threadfence();
            g_state[bid] = 1;
            int i = bid - 1;
            while (true) {
                int st;
                while ((st = g_state[i]) == 0) { }
                if (st == 2) { exc += g_prefval[i]; break; }
                exc += g_aggval[i];
                i--;
            }
            g_prefval[bid] = exc + total;
            __threadfence();
            g_state[bid] = 2;
        }
        s_exc = exc;
    }
    __syncthreads();

    int run = x - tsum + s_warp[w] + s_exc;
#pragma unroll
    for (int j = 0; j < 4; j++) {
        int idx = base + j;
        if (idx < N) {
            g_off[idx]  = run;
            g_cur[idx]  = run;
            g_dinv[idx] = rsqrtf((float)(v[j] + 1));   // +1 self loop
            run += v[j];
        }
    }
}

__global__ void fill_kernel(const int* __restrict__ ei, int E) {
    int e = blockIdx.x * blockDim.x + threadIdx.x;
    if (e >= E) return;
    int s, d;
    if (g_is64) { s = ei[2 * e]; d = ei[2 * E + 2 * e]; }
    else        { s = ei[e];     d = ei[E + e]; }
    int pos = atomicAdd(&g_cur[d], 1);
    g_csr[pos] = s;
}

// ---------------------------------------------------------------------------
// GEMM: 64-node tile per block (256 threads, 4x4 micro-tile).
// TRANSFORM: input = relu(prev_acc * dinv + prev_bias), loaded from g_acc.
// Writes ONLY g_h (fp16 messages, pre-scaled by dinv of the source node).
// ---------------------------------------------------------------------------
template <int FIN, bool TRANSFORM>
__global__ void gemm_kernel(const float* __restrict__ Xin,
                            const float* __restrict__ W,
                            const float* __restrict__ bias_prev,
                            int N) {
    __shared__ float xsT[FIN][68];
    __shared__ float ws[FIN][H];

    const float* __restrict__ X = TRANSFORM ? (const float*)g_acc : Xin;

    int node0 = blockIdx.x * 64;
    int t = threadIdx.x;

    for (int i = t; i < FIN * H; i += 256) ws[i / H][i % H] = W[i];

    for (int i = t; i < 64 * FIN; i += 256) {
        int n = i / FIN, k = i % FIN;
        int gn = node0 + n;
        float v = 0.f;
        if (gn < N) {
            v = X[gn * FIN + k];
            if (TRANSFORM) v = fmaxf(fmaf(v, g_dinv[gn], bias_prev[k]), 0.f);
        }
        xsT[k][n] = v;
    }
    __syncthreads();

    int tx = t & 15, ty = t >> 4;
    float acc[4][4];
#pragma unroll
    for (int i = 0; i < 4; i++)
#pragma unroll
        for (int j = 0; j < 4; j++) acc[i][j] = 0.f;

#pragma unroll
    for (int k = 0; k < FIN; k++) {
        float4 xv = *(const float4*)&xsT[k][ty * 4];
        float4 wv = *(const float4*)&ws[k][tx * 4];
        float xa[4] = {xv.x, xv.y, xv.z, xv.w};
        float wa[4] = {wv.x, wv.y, wv.z, wv.w};
#pragma unroll
        for (int i = 0; i < 4; i++)
#pragma unroll
            for (int j = 0; j < 4; j++)
                acc[i][j] = fmaf(xa[i], wa[j], acc[i][j]);
    }

#pragma unroll
    for (int i = 0; i < 4; i++) {
        int gn = node0 + ty * 4 + i;
        if (gn < N) {
            float di = g_dinv[gn];
            __half2* hp = (__half2*)(g_h + (size_t)gn * H + tx * 4);
            hp[0] = __floats2half2_rn(acc[i][0] * di, acc[i][1] * di);
            hp[1] = __floats2half2_rn(acc[i][2] * di, acc[i][3] * di);
        }
    }
}

// ---------------------------------------------------------------------------
// CSR aggregation: 8 threads/node, each owns 8 features (16B fp16 chunk).
// Edge loop unrolled x4 for MLP. Self message initialized from g_h.
// FINAL: fold layer-3 epilogue + mean pooling (no g_acc write).
// ---------------------------------------------------------------------------
__device__ __forceinline__ void accum_row(float4& a0, float4& a1, uint4 raw) {
    float2 f0 = __half22float2(*reinterpret_cast<__half2*>(&raw.x));
    float2 f1 = __half22float2(*reinterpret_cast<__half2*>(&raw.y));
    float2 f2 = __half22float2(*reinterpret_cast<__half2*>(&raw.z));
    float2 f3 = __half22float2(*reinterpret_cast<__half2*>(&raw.w));
    a0.x += f0.x; a0.y += f0.y; a0.z += f1.x; a0.w += f1.y;
    a1.x += f2.x; a1.y += f2.y; a1.z += f3.x; a1.w += f3.y;
}

template <bool FINAL>
__global__ void aggregate_kernel(int N) {
    __shared__ float s_col[H];
    if (FINAL) {
        if (threadIdx.x < H) s_col[threadIdx.x] = 0.f;
        __syncthreads();
    }

    int idx = blockIdx.x * blockDim.x + threadIdx.x;
    int node = idx >> 3;
    int lane = idx & 7;

    if (node < N) {
        int start = g_off[node];
        int cnt = g_cnt[node];

        const __half* gh = g_h;
        float4 a0 = make_float4(0.f, 0.f, 0.f, 0.f);
        float4 a1 = make_float4(0.f, 0.f, 0.f, 0.f);
        // self message
        accum_row(a0, a1, __ldg((const uint4*)(gh + (size_t)node * H) + lane));

        int e = start, end = start + cnt;
        for (; e + 4 <= end; e += 4) {
            int s0 = __ldg(&g_csr[e]);
            int s1 = __ldg(&g_csr[e + 1]);
            int s2 = __ldg(&g_csr[e + 2]);
            int s3 = __ldg(&g_csr[e + 3]);
            uint4 r0 = __ldg((const uint4*)(gh + (size_t)s0 * H) + lane);
            uint4 r1 = __ldg((const uint4*)(gh + (size_t)s1 * H) + lane);
            uint4 r2 = __ldg((const uint4*)(gh + (size_t)s2 * H) + lane);
            uint4 r3 = __ldg((const uint4*)(gh + (size_t)s3 * H) + lane);
            accum_row(a0, a1, r0);
            accum_row(a0, a1, r1);
            accum_row(a0, a1, r2);
            accum_row(a0, a1, r3);
        }
        for (; e < end; e++) {
            int s = __ldg(&g_csr[e]);
            accum_row(a0, a1, __ldg((const uint4*)(gh + (size_t)s * H) + lane));
        }

        if (FINAL) {
            float di = g_dinv[node];
            atomicAdd(&s_col[lane * 8 + 0], a0.x * di);
            atomicAdd(&s_col[lane * 8 + 1], a0.y * di);
            atomicAdd(&s_col[lane * 8 + 2], a0.z * di);
            atomicAdd(&s_col[lane * 8 + 3], a0.w * di);
            atomicAdd(&s_col[lane * 8 + 4], a1.x * di);
            atomicAdd(&s_col[lane * 8 + 5], a1.y * di);
            atomicAdd(&s_col[lane * 8 + 6], a1.z * di);
            atomicAdd(&s_col[lane * 8 + 7], a1.w * di);
        } else {
            *(float4*)(g_acc + (size_t)node * H + lane * 8)     = a0;
            *(float4*)(g_acc + (size_t)node * H + lane * 8 + 4) = a1;
        }
    }

    if (FINAL) {
        __syncthreads();
        if (threadIdx.x < H) atomicAdd(&g_colsum[threadIdx.x], s_col[threadIdx.x]);
    }
}

// out = (colsum/N + b3) . fcW + fcb
__global__ void final_kernel(const float* __restrict__ b3,
                             const float* __restrict__ fcW,
                             const float* __restrict__ fcb,
                             float* __restrict__ out, int N) {
    int f = threadIdx.x;  // 64 threads
    float v = (g_colsum[f] / (float)N + b3[f]) * fcW[f];
#pragma unroll
    for (int o = 16; o > 0; o >>= 1) v += __shfl_down_sync(0xffffffffu, v, o);
    __shared__ float p[2];
    if ((f & 31) == 0) p[f >> 5] = v;
    __syncthreads();
    if (f == 0) out[0] = p[0] + p[1] + fcb[0];
}

extern "C" void kernel_launch(void* const* d_in, const int* in_sizes, int n_in,
                              void* d_out, int out_size) {
    const float* x   = (const float*)d_in[0];
    const void*  ei  = d_in[1];
    const float* W1  = (const float*)d_in[2];
    const float* b1  = (const float*)d_in[3];
    const float* W2  = (const float*)d_in[4];
    const float* b2  = (const float*)d_in[5];
    const float* W3  = (const float*)d_in[6];
    const float* b3  = (const float*)d_in[7];
    const float* fcW = (const float*)d_in[8];
    const float* fcb = (const float*)d_in[9];
    float* out = (float*)d_out;

    int FIN1 = in_sizes[2] / H;      // 10
    int N = in_sizes[0] / FIN1;      // 50000
    int E = in_sizes[1] / 2;         // 800000

    int SB = (N + 1023) / 1024;      // scan blocks (<=64)
    int gblocks = (N + 63) / 64;
    int ablocks = (N * 8 + 255) / 256;

    zero_kernel<<<(N + 255) / 256, 256>>>((const unsigned int*)ei, N);
    hist_kernel<<<(E + 255) / 256, 256>>>((const int*)ei, E);
    scan_kernel<<<SB, 256>>>(N);
    fill_kernel<<<(E + 255) / 256, 256>>>((const int*)ei, E);

    gemm_kernel<10, false><<<gblocks, 256>>>(x, W1, nullptr, N);
    aggregate_kernel<false><<<ablocks, 256>>>(N);

    gemm_kernel<64, true><<<gblocks, 256>>>(nullptr, W2, b1, N);
    aggregate_kernel<false><<<ablocks, 256>>>(N);

    gemm_kernel<64, true><<<gblocks, 256>>>(nullptr, W3, b2, N);
    aggregate_kernel<true><<<ablocks, 256>>>(N);

    final_kernel<<<1, 64>>>(b3, fcW, fcb, out, N);
}